// round 12
// baseline (speedup 1.0000x reference)
#include <cuda_runtime.h>

#define NN 2048
#define EE 65536
#define SEQL 5
#define IND 32
#define HID 64
#define OUTD 16

typedef unsigned long long ull;

// ---------------- scratch (device globals; no allocs allowed) ----------------
__device__ float d_deg[NN];
__device__ float d_dinv[NN];
__device__ float d_dself[NN];
__device__ int   d_count[NN];
__device__ int   d_cursor[NN];
__device__ int   d_rowptr[NN + 1];
__device__ int   d_csr_src[EE];
__device__ float d_csr_w[EE];
__device__ float d_Wz[IND * HID], d_Wh[IND * HID];            // folded gate weights
__device__ float d_bz[HID], d_bh[HID];
__device__ __align__(16) float d_emb[NN * HID];
__device__ __align__(16) float d_r1[NN * HID];
__device__ __align__(16) float d_av[NN * HID];                // emb@Wi1[:64]+bi1
__device__ __align__(16) float d_bv[NN * HID];                // emb@Wi1[64:]

// ---------------- f32x2 packed helpers (Blackwell double-rate fp32) ----------
__device__ __forceinline__ ull f2_add(ull a, ull b) {
    ull r; asm("add.rn.f32x2 %0,%1,%2;" : "=l"(r) : "l"(a), "l"(b)); return r;
}
__device__ __forceinline__ ull f2_fma(ull a, ull b, ull c) {
    ull r; asm("fma.rn.f32x2 %0,%1,%2,%3;" : "=l"(r) : "l"(a), "l"(b), "l"(c)); return r;
}
__device__ __forceinline__ ull f2_relu(ull a) {
    float lo, hi;
    asm("mov.b64 {%0,%1},%2;" : "=f"(lo), "=f"(hi) : "l"(a));
    lo = fmaxf(lo, 0.f); hi = fmaxf(hi, 0.f);
    ull r; asm("mov.b64 %0,{%1,%2};" : "=l"(r) : "f"(lo), "f"(hi)); return r;
}

// ------- init + independent gate-weight fold (Wz=Wcz@Wlz[:64], etc.) ---------
__global__ void k_init(const float* __restrict__ Wcz, const float* __restrict__ bcz,
                       const float* __restrict__ Wlz, const float* __restrict__ blz,
                       const float* __restrict__ Wch, const float* __restrict__ bch,
                       const float* __restrict__ Wlh, const float* __restrict__ blh) {
    int gid = blockIdx.x * 1024 + threadIdx.x;          // 2048 threads
    d_deg[gid] = 0.0f;
    d_count[gid] = 0;
    {   // one folded weight element per thread (2048 = IND*HID)
        int i = gid >> 6, j = gid & 63;
        float az = 0.f, ah = 0.f;
#pragma unroll 4
        for (int k = 0; k < HID; k++) {
            az += Wcz[i * HID + k] * Wlz[k * HID + j];
            ah += Wch[i * HID + k] * Wlh[k * HID + j];
        }
        d_Wz[gid] = az; d_Wh[gid] = ah;
    }
    if (gid < HID) {
        float bz = blz[gid], bh = blh[gid];
#pragma unroll 4
        for (int k = 0; k < HID; k++) {
            bz += bcz[k] * Wlz[k * HID + gid];
            bh += bch[k] * Wlh[k * HID + gid];
        }
        d_bz[gid] = bz; d_bh[gid] = bh;
    }
}

// 128 blocks x 256 threads, 2 edges/thread: full-chip coverage, returnless REDs
__global__ void __launch_bounds__(256) k_degcount(const int* __restrict__ ei,
                                                  const float* __restrict__ ew) {
    int tid = blockIdx.x * 256 + threadIdx.x;           // 32768 threads
    int e0 = tid * 2;
    int2  d = *(const int2*)(ei + EE + e0);
    float2 w = *(const float2*)(ew + e0);
    atomicAdd(&d_deg[d.x], w.x);
    atomicAdd(&d_deg[d.y], w.y);
    atomicAdd(&d_count[d.x], 1);
    atomicAdd(&d_count[d.y], 1);
}

// 1 block / 1024 threads: dinv+dself, scan->rowptr, cursor=rowptr
__global__ void k_scan() {
    int t = threadIdx.x;
    __shared__ int s[NN];
    for (int i = t; i < NN; i += 1024) {
        float di = rsqrtf(d_deg[i] + 1.0f);            // +1 self-loop
        d_dinv[i] = di; d_dself[i] = di * di;
        s[i] = d_count[i];
    }
    __syncthreads();
    for (int off = 1; off < NN; off <<= 1) {
        int i1 = t + 1024;
        int v0 = (t >= off)  ? s[t - off]  : 0;
        int v1 = (i1 >= off) ? s[i1 - off] : 0;
        __syncthreads();
        s[t] += v0; s[i1] += v1;
        __syncthreads();
    }
    d_rowptr[t + 1] = s[t];
    d_rowptr[t + 1025] = s[t + 1024];
    d_cursor[t + 1] = s[t];
    if (t < 1023) d_cursor[t + 1025] = s[t + 1024];
    if (t == 0) { d_rowptr[0] = 0; d_cursor[0] = 0; }
}

// 128 blocks x 256 threads, 2 edges/thread (2 independent ATOMGs in flight)
__global__ void __launch_bounds__(256) k_scatter(const int* __restrict__ ei,
                                                 const float* __restrict__ ew) {
    int tid = blockIdx.x * 256 + threadIdx.x;           // 32768 threads
    int e0 = tid * 2;
    int2  sv = *(const int2*)(ei + e0);
    int2  dv = *(const int2*)(ei + EE + e0);
    float2 wv = *(const float2*)(ew + e0);
    int p0 = atomicAdd(&d_cursor[dv.x], 1);
    int p1 = atomicAdd(&d_cursor[dv.y], 1);
    d_csr_src[p0] = sv.x;
    d_csr_src[p1] = sv.y;
    d_csr_w[p0] = d_dinv[sv.x] * wv.x * d_dinv[dv.x];
    d_csr_w[p1] = d_dinv[sv.y] * wv.y * d_dinv[dv.y];
}

// ------- fused per-node: spmm1(x,160 cols) -> gates -> emb -> av/bv ----------
__global__ void __launch_bounds__(160) k_node(const float* __restrict__ x,
                                              const float* __restrict__ Wred,
                                              const float* __restrict__ bred,
                                              const float* __restrict__ Wi1,
                                              const float* __restrict__ bi1) {
    int n = blockIdx.x;
    int tid = threadIdx.x;
    int t = tid >> 5, c = tid & 31;
    __shared__ int   ss[160];
    __shared__ float swt[160];
    __shared__ float spm[SEQL * IND];      // aggregated x for node n
    __shared__ float sh[SEQL * HID];       // hs
    __shared__ float se[HID];              // emb
    int r0 = d_rowptr[n], r1 = d_rowptr[n + 1];
    const float* xt = x + t * NN * IND + c;
    float a0 = d_dself[n] * xt[n * IND];
    float a1 = 0.f, a2 = 0.f, a3 = 0.f;
    for (int base = r0; base < r1; base += 160) {
        int m = min(160, r1 - base);
        if (tid < m) { ss[tid] = d_csr_src[base + tid]; swt[tid] = d_csr_w[base + tid]; }
        __syncthreads();
        int k = 0;
        for (; k + 4 <= m; k += 4) {        // 4 gathers in flight, 4 indep FMA chains
            a0 += swt[k + 0] * xt[ss[k + 0] * IND];
            a1 += swt[k + 1] * xt[ss[k + 1] * IND];
            a2 += swt[k + 2] * xt[ss[k + 2] * IND];
            a3 += swt[k + 3] * xt[ss[k + 3] * IND];
        }
        for (; k < m; k++) a0 += swt[k] * xt[ss[k] * IND];
        __syncthreads();
    }
    spm[t * IND + c] = (a0 + a1) + (a2 + a3);
    __syncthreads();

    // gates: 320 outputs, 2 per thread (p and p+160); p = tg*64 + j
#pragma unroll
    for (int half = 0; half < 2; half++) {
        int p = tid + half * 160;
        int tg = p >> 6, j = p & 63;
        float az = d_bz[j], ah = d_bh[j];
#pragma unroll
        for (int k = 0; k < IND; k++) {
            float pv = spm[tg * IND + k];
            az += pv * d_Wz[k * HID + j];
            ah += pv * d_Wh[k * HID + j];
        }
        float zg = 1.f / (1.f + expf(-az));
        sh[p] = (1.f - zg) * tanhf(ah);
    }
    __syncthreads();

    // emb = sh @ Wred + bred (64 outputs, threads 0..63)
    if (tid < HID) {
        float b0 = bred[tid], b1 = 0.f, b2 = 0.f, b3 = 0.f;
#pragma unroll 4
        for (int k = 0; k < SEQL * HID; k += 4) {
            b0 += sh[k + 0] * Wred[(k + 0) * HID + tid];
            b1 += sh[k + 1] * Wred[(k + 1) * HID + tid];
            b2 += sh[k + 2] * Wred[(k + 2) * HID + tid];
            b3 += sh[k + 3] * Wred[(k + 3) * HID + tid];
        }
        float e = (b0 + b1) + (b2 + b3);
        d_emb[n * HID + tid] = e;
        se[tid] = e;
    }
    __syncthreads();

    // av = emb@Wi1[:64]+bi1 ; bv = emb@Wi1[64:]
    if (tid < HID) {
        float aa = bi1[tid], bb = 0.f;
#pragma unroll 4
        for (int k = 0; k < HID; k++) {
            float e = se[k];
            aa += e * Wi1[k * HID + tid];
            bb += e * Wi1[(HID + k) * HID + tid];
        }
        d_av[n * HID + tid] = aa;
        d_bv[n * HID + tid] = bb;
    }
}

// ------- fused gcn layer 1: spmm64(emb) -> @Wc1 -> LN -> relu -> r1 ----------
__global__ void __launch_bounds__(64) k_gcn1(const float* __restrict__ Wc1, const float* __restrict__ bc1,
                                             const float* __restrict__ g1, const float* __restrict__ be1) {
    int n = blockIdx.x, j = threadIdx.x;
    __shared__ int   ss[64];
    __shared__ float swt[64];
    __shared__ float sa[HID];
    __shared__ float rbuf[4];
    int r0 = d_rowptr[n], r1 = d_rowptr[n + 1];
    float a0 = d_dself[n] * d_emb[n * HID + j];
    float a1 = 0.f, a2 = 0.f, a3 = 0.f;
    for (int base = r0; base < r1; base += 64) {
        int m = min(64, r1 - base);
        if (j < m) { ss[j] = d_csr_src[base + j]; swt[j] = d_csr_w[base + j]; }
        __syncthreads();
        int k = 0;
        for (; k + 4 <= m; k += 4) {
            a0 += swt[k + 0] * d_emb[ss[k + 0] * HID + j];
            a1 += swt[k + 1] * d_emb[ss[k + 1] * HID + j];
            a2 += swt[k + 2] * d_emb[ss[k + 2] * HID + j];
            a3 += swt[k + 3] * d_emb[ss[k + 3] * HID + j];
        }
        for (; k < m; k++) a0 += swt[k] * d_emb[ss[k] * HID + j];
        __syncthreads();
    }
    sa[j] = (a0 + a1) + (a2 + a3);
    __syncthreads();
    float h = bc1[j];
#pragma unroll
    for (int k = 0; k < HID; k++) h += sa[k] * Wc1[k * HID + j];
    float v = h;
#pragma unroll
    for (int o = 16; o > 0; o >>= 1) v += __shfl_xor_sync(0xffffffffu, v, o);
    if ((j & 31) == 0) rbuf[j >> 5] = v;
    __syncthreads();
    float mu = (rbuf[0] + rbuf[1]) * (1.f / 64.f);
    float d = h - mu;
    float v2 = d * d;
#pragma unroll
    for (int o = 16; o > 0; o >>= 1) v2 += __shfl_xor_sync(0xffffffffu, v2, o);
    if ((j & 31) == 0) rbuf[(j >> 5) + 2] = v2;
    __syncthreads();
    float var = (rbuf[2] + rbuf[3]) * (1.f / 64.f);
    d_r1[n * HID + j] = fmaxf(0.f, d * rsqrtf(var + 1e-5f) * g1[j] + be1[j]);
}

// ------- fused gcn layer 2: spmm64(r1) -> @Wc2 -> LN -> relu -> @Wout --------
__global__ void __launch_bounds__(64) k_gcn2(const float* __restrict__ Wc2, const float* __restrict__ bc2,
                                             const float* __restrict__ g2, const float* __restrict__ be2,
                                             const float* __restrict__ Wout, const float* __restrict__ bout,
                                             float* __restrict__ outp) {
    int n = blockIdx.x, j = threadIdx.x;
    __shared__ int   ss[64];
    __shared__ float swt[64];
    __shared__ float sa[HID];
    __shared__ float sr[HID];
    __shared__ float rbuf[4];
    int r0 = d_rowptr[n], r1 = d_rowptr[n + 1];
    float a0 = d_dself[n] * d_r1[n * HID + j];
    float a1 = 0.f, a2 = 0.f, a3 = 0.f;
    for (int base = r0; base < r1; base += 64) {
        int m = min(64, r1 - base);
        if (j < m) { ss[j] = d_csr_src[base + j]; swt[j] = d_csr_w[base + j]; }
        __syncthreads();
        int k = 0;
        for (; k + 4 <= m; k += 4) {
            a0 += swt[k + 0] * d_r1[ss[k + 0] * HID + j];
            a1 += swt[k + 1] * d_r1[ss[k + 1] * HID + j];
            a2 += swt[k + 2] * d_r1[ss[k + 2] * HID + j];
            a3 += swt[k + 3] * d_r1[ss[k + 3] * HID + j];
        }
        for (; k < m; k++) a0 += swt[k] * d_r1[ss[k] * HID + j];
        __syncthreads();
    }
    sa[j] = (a0 + a1) + (a2 + a3);
    __syncthreads();
    float h = bc2[j];
#pragma unroll
    for (int k = 0; k < HID; k++) h += sa[k] * Wc2[k * HID + j];
    float v = h;
#pragma unroll
    for (int o = 16; o > 0; o >>= 1) v += __shfl_xor_sync(0xffffffffu, v, o);
    if ((j & 31) == 0) rbuf[j >> 5] = v;
    __syncthreads();
    float mu = (rbuf[0] + rbuf[1]) * (1.f / 64.f);
    float d = h - mu;
    float v2 = d * d;
#pragma unroll
    for (int o = 16; o > 0; o >>= 1) v2 += __shfl_xor_sync(0xffffffffu, v2, o);
    if ((j & 31) == 0) rbuf[(j >> 5) + 2] = v2;
    __syncthreads();
    float var = (rbuf[2] + rbuf[3]) * (1.f / 64.f);
    float r = fmaxf(0.f, d * rsqrtf(var + 1e-5f) * g2[j] + be2[j]);
    sr[j] = r;
    __syncthreads();
    if (j < OUTD) {
        float o = bout[j];
#pragma unroll
        for (int k = 0; k < HID; k++) o += sr[k] * Wout[k * OUTD + j];
        outp[n * OUTD + j] = o;
    }
}

// ---------------- scores: relu(a_i + b_j) . w  (f32x2 packed) ----------------
// Pipe-balanced at ~28K cyc: fma-pipe == alu-pipe == issue. Do not "optimize"
// relu onto the fma pipe — it unbalances to 42K cyc.
__global__ void __launch_bounds__(256) k_scores(const float* __restrict__ Wi2,
                                                const float* __restrict__ bi2,
                                                float* __restrict__ outp) {
    __shared__ __align__(16) float sA[64][66];
    __shared__ __align__(16) float sB[64][66];
    __shared__ __align__(16) float sW[64];
    int tx = threadIdx.x, ty = threadIdx.y;
    int tid = ty * 16 + tx;
    int i0 = blockIdx.y * 64, j0 = blockIdx.x * 64;
    for (int f = tid; f < 64 * 32; f += 256) {
        int r = f >> 5, c2 = f & 31;
        float2 va = *(const float2*)&d_av[(i0 + r) * HID + 2 * c2];
        float2 vb = *(const float2*)&d_bv[(j0 + r) * HID + 2 * c2];
        *(float2*)&sA[r][2 * c2] = va;
        *(float2*)&sB[r][2 * c2] = vb;
    }
    if (tid < 64) sW[tid] = Wi2[tid];
    __syncthreads();

    ull acc[4][4];
#pragma unroll
    for (int r = 0; r < 4; r++)
#pragma unroll
        for (int c = 0; c < 4; c++) acc[r][c] = 0ull;

#pragma unroll 4
    for (int h = 0; h < 32; h++) {
        ull w2 = *(const ull*)&sW[2 * h];
        ull A[4], B[4];
#pragma unroll
        for (int r = 0; r < 4; r++) A[r] = *(const ull*)&sA[ty * 4 + r][2 * h];
#pragma unroll
        for (int c = 0; c < 4; c++) B[c] = *(const ull*)&sB[tx * 4 + c][2 * h];
#pragma unroll
        for (int r = 0; r < 4; r++)
#pragma unroll
            for (int c = 0; c < 4; c++) {
                ull t = f2_add(A[r], B[c]);
                t = f2_relu(t);
                acc[r][c] = f2_fma(t, w2, acc[r][c]);
            }
    }

    float bb = bi2[0];
    float* sc = outp + NN * OUTD;
#pragma unroll
    for (int r = 0; r < 4; r++) {
        float4 o;
        float res[4];
#pragma unroll
        for (int c = 0; c < 4; c++) {
            float lo, hi;
            asm("mov.b64 {%0,%1},%2;" : "=f"(lo), "=f"(hi) : "l"(acc[r][c]));
            res[c] = lo + hi + bb;
        }
        o.x = res[0]; o.y = res[1]; o.z = res[2]; o.w = res[3];
        *(float4*)&sc[(i0 + ty * 4 + r) * NN + j0 + tx * 4] = o;
    }
}

// ---------------- launcher ----------------------------------------------------
extern "C" void kernel_launch(void* const* d_in, const int* in_sizes, int n_in,
                              void* d_out, int out_size) {
    (void)out_size;
    const float* x = nullptr;
    const int* ei = nullptr;
    const float* ew = nullptr;
    const float* W[28];
    int wi = 0;
    for (int i = 0; i < n_in; i++) {
        int s = in_sizes[i];
        if (s == SEQL * NN * IND)      x  = (const float*)d_in[i];
        else if (s == 2 * EE)          ei = (const int*)d_in[i];
        else if (s == EE)              ew = (const float*)d_in[i];
        else if (wi < 28)              W[wi++] = (const float*)d_in[i];
    }
    const float *Wcz = W[0],  *bcz = W[1],  *Wlz = W[2],  *blz = W[3];
    const float *Wch = W[8],  *bch = W[9],  *Wlh = W[10], *blh = W[11];
    const float *Wred = W[12], *bred = W[13];
    const float *Wc1 = W[14], *bc1 = W[15], *Wc2 = W[16], *bc2 = W[17];
    const float *g1 = W[18],  *be1 = W[19], *g2 = W[20],  *be2 = W[21];
    const float *Wout = W[22], *bout = W[23];
    const float *Wi1 = W[24], *bi1 = W[25], *Wi2 = W[26], *bi2 = W[27];
    float* outp = (float*)d_out;

    k_init<<<2, 1024>>>(Wcz, bcz, Wlz, blz, Wch, bch, Wlh, blh);
    k_degcount<<<128, 256>>>(ei, ew);
    k_scan<<<1, 1024>>>();
    k_scatter<<<128, 256>>>(ei, ew);
    k_node<<<NN, 160>>>(x, Wred, bred, Wi1, bi1);
    k_gcn1<<<NN, 64>>>(Wc1, bc1, g1, be1);
    k_gcn2<<<NN, 64>>>(Wc2, bc2, g2, be2, Wout, bout, outp);
    k_scores<<<dim3(NN / 64, NN / 64), dim3(16, 16)>>>(Wi2, bi2, outp);
}

// round 13
// speedup vs baseline: 1.5013x; 1.5013x over previous
#include <cuda_runtime.h>

#define NN 2048
#define EE 65536
#define SEQL 5
#define IND 32
#define HID 64
#define OUTD 16

typedef unsigned long long ull;

// ---------------- scratch (device globals; no allocs allowed) ----------------
__device__ float d_deg[NN];
__device__ float d_dinv[NN];
__device__ float d_dself[NN];
__device__ int   d_count[NN];
__device__ int   d_cursor[NN];
__device__ int   d_rowptr[NN + 1];
__device__ int   d_csr_src[EE];
__device__ float d_csr_w[EE];
__device__ float d_Wz[IND * HID], d_Wh[IND * HID];            // folded gate weights
__device__ float d_bz[HID], d_bh[HID];
__device__ __align__(16) float d_emb[NN * HID];
__device__ __align__(16) float d_r1[NN * HID];
__device__ __align__(16) float d_av[NN * HID];                // emb@Wi1[:64]+bi1
__device__ __align__(16) float d_bv[NN * HID];                // emb@Wi1[64:]

// ---------------- f32x2 packed helpers (Blackwell double-rate fp32) ----------
__device__ __forceinline__ ull f2_add(ull a, ull b) {
    ull r; asm("add.rn.f32x2 %0,%1,%2;" : "=l"(r) : "l"(a), "l"(b)); return r;
}
__device__ __forceinline__ ull f2_fma(ull a, ull b, ull c) {
    ull r; asm("fma.rn.f32x2 %0,%1,%2,%3;" : "=l"(r) : "l"(a), "l"(b), "l"(c)); return r;
}
__device__ __forceinline__ ull f2_relu(ull a) {
    float lo, hi;
    asm("mov.b64 {%0,%1},%2;" : "=f"(lo), "=f"(hi) : "l"(a));
    lo = fmaxf(lo, 0.f); hi = fmaxf(hi, 0.f);
    ull r; asm("mov.b64 %0,{%1,%2};" : "=l"(r) : "f"(lo), "f"(hi)); return r;
}

// ------- init (zero deg/count) + gate-weight fold, spread over 16 SMs --------
__global__ void __launch_bounds__(128) k_init(
        const float* __restrict__ Wcz, const float* __restrict__ bcz,
        const float* __restrict__ Wlz, const float* __restrict__ blz,
        const float* __restrict__ Wch, const float* __restrict__ bch,
        const float* __restrict__ Wlh, const float* __restrict__ blh) {
    int gid = blockIdx.x * 128 + threadIdx.x;           // 2048 threads (16 x 128)
    d_deg[gid] = 0.0f;
    d_count[gid] = 0;
    {   // one folded weight element per thread (2048 = IND*HID)
        int i = gid >> 6, j = gid & 63;
        float a0 = 0.f, a1 = 0.f, h0 = 0.f, h1 = 0.f;
#pragma unroll 8
        for (int k = 0; k < HID; k += 2) {
            a0 += Wcz[i * HID + k]     * Wlz[k * HID + j];
            a1 += Wcz[i * HID + k + 1] * Wlz[(k + 1) * HID + j];
            h0 += Wch[i * HID + k]     * Wlh[k * HID + j];
            h1 += Wch[i * HID + k + 1] * Wlh[(k + 1) * HID + j];
        }
        d_Wz[gid] = a0 + a1; d_Wh[gid] = h0 + h1;
    }
    if (gid < HID) {
        float bz = blz[gid], bh = blh[gid];
#pragma unroll 4
        for (int k = 0; k < HID; k++) {
            bz += bcz[k] * Wlz[k * HID + gid];
            bh += bch[k] * Wlh[k * HID + gid];
        }
        d_bz[gid] = bz; d_bh[gid] = bh;
    }
}

// 64 x 1024, 1 edge/thread (measured-best config: 32 warps/SM hide ATOMG)
__global__ void __launch_bounds__(1024) k_degcount(const int* __restrict__ ei,
                                                   const float* __restrict__ ew) {
    int e = blockIdx.x * 1024 + threadIdx.x;
    int dd = ei[EE + e];
    atomicAdd(&d_deg[dd], ew[e]);
    atomicAdd(&d_count[dd], 1);
}

// 1 block / 1024 threads: dinv+dself, scan->rowptr, cursor=rowptr
__global__ void k_scan() {
    int t = threadIdx.x;
    __shared__ int s[NN];
    for (int i = t; i < NN; i += 1024) {
        float di = rsqrtf(d_deg[i] + 1.0f);            // +1 self-loop
        d_dinv[i] = di; d_dself[i] = di * di;
        s[i] = d_count[i];
    }
    __syncthreads();
    for (int off = 1; off < NN; off <<= 1) {
        int i1 = t + 1024;
        int v0 = (t >= off)  ? s[t - off]  : 0;
        int v1 = (i1 >= off) ? s[i1 - off] : 0;
        __syncthreads();
        s[t] += v0; s[i1] += v1;
        __syncthreads();
    }
    d_rowptr[t + 1] = s[t];
    d_rowptr[t + 1025] = s[t + 1024];
    d_cursor[t + 1] = s[t];
    if (t < 1023) d_cursor[t + 1025] = s[t + 1024];
    if (t == 0) { d_rowptr[0] = 0; d_cursor[0] = 0; }
}

// 64 x 1024, 1 edge/thread (measured best: 7.9us)
__global__ void __launch_bounds__(1024) k_scatter(const int* __restrict__ ei,
                                                  const float* __restrict__ ew) {
    int e = blockIdx.x * 1024 + threadIdx.x;
    int sIdx = ei[e], dd = ei[EE + e];
    int pos = atomicAdd(&d_cursor[dd], 1);
    d_csr_src[pos] = sIdx;
    d_csr_w[pos] = d_dinv[sIdx] * ew[e] * d_dinv[dd];
}

// ------- fused per-node: spmm1(x,160 cols) -> gates -> emb -> av/bv ----------
__global__ void __launch_bounds__(160) k_node(const float* __restrict__ x,
                                              const float* __restrict__ Wred,
                                              const float* __restrict__ bred,
                                              const float* __restrict__ Wi1,
                                              const float* __restrict__ bi1) {
    int n = blockIdx.x;
    int tid = threadIdx.x;
    int t = tid >> 5, c = tid & 31;
    __shared__ int   ss[160];
    __shared__ float swt[160];
    __shared__ float spm[SEQL * IND];      // aggregated x for node n
    __shared__ float sh[SEQL * HID];       // hs
    __shared__ float se[HID];              // emb
    int r0 = d_rowptr[n], r1 = d_rowptr[n + 1];
    const float* xt = x + t * NN * IND + c;
    float a0 = d_dself[n] * xt[n * IND];
    float a1 = 0.f, a2 = 0.f, a3 = 0.f;
    for (int base = r0; base < r1; base += 160) {
        int m = min(160, r1 - base);
        if (tid < m) { ss[tid] = d_csr_src[base + tid]; swt[tid] = d_csr_w[base + tid]; }
        __syncthreads();
        int k = 0;
        for (; k + 4 <= m; k += 4) {        // 4 gathers in flight, 4 indep FMA chains
            a0 += swt[k + 0] * xt[ss[k + 0] * IND];
            a1 += swt[k + 1] * xt[ss[k + 1] * IND];
            a2 += swt[k + 2] * xt[ss[k + 2] * IND];
            a3 += swt[k + 3] * xt[ss[k + 3] * IND];
        }
        for (; k < m; k++) a0 += swt[k] * xt[ss[k] * IND];
        __syncthreads();
    }
    spm[t * IND + c] = (a0 + a1) + (a2 + a3);
    __syncthreads();

    // gates: 320 outputs, 2 per thread (p and p+160); p = tg*64 + j
#pragma unroll
    for (int half = 0; half < 2; half++) {
        int p = tid + half * 160;
        int tg = p >> 6, j = p & 63;
        float az = d_bz[j], ah = d_bh[j];
#pragma unroll
        for (int k = 0; k < IND; k++) {
            float pv = spm[tg * IND + k];
            az += pv * d_Wz[k * HID + j];
            ah += pv * d_Wh[k * HID + j];
        }
        float zg = 1.f / (1.f + expf(-az));
        sh[p] = (1.f - zg) * tanhf(ah);
    }
    __syncthreads();

    // emb = sh @ Wred + bred (64 outputs, threads 0..63)
    if (tid < HID) {
        float b0 = bred[tid], b1 = 0.f, b2 = 0.f, b3 = 0.f;
#pragma unroll 4
        for (int k = 0; k < SEQL * HID; k += 4) {
            b0 += sh[k + 0] * Wred[(k + 0) * HID + tid];
            b1 += sh[k + 1] * Wred[(k + 1) * HID + tid];
            b2 += sh[k + 2] * Wred[(k + 2) * HID + tid];
            b3 += sh[k + 3] * Wred[(k + 3) * HID + tid];
        }
        float e = (b0 + b1) + (b2 + b3);
        d_emb[n * HID + tid] = e;
        se[tid] = e;
    }
    __syncthreads();

    // av = emb@Wi1[:64]+bi1 ; bv = emb@Wi1[64:]
    if (tid < HID) {
        float aa = bi1[tid], bb = 0.f;
#pragma unroll 4
        for (int k = 0; k < HID; k++) {
            float e = se[k];
            aa += e * Wi1[k * HID + tid];
            bb += e * Wi1[(HID + k) * HID + tid];
        }
        d_av[n * HID + tid] = aa;
        d_bv[n * HID + tid] = bb;
    }
}

// ------- fused gcn layer 1: spmm64(emb) -> @Wc1 -> LN -> relu -> r1 ----------
__global__ void __launch_bounds__(64) k_gcn1(const float* __restrict__ Wc1, const float* __restrict__ bc1,
                                             const float* __restrict__ g1, const float* __restrict__ be1) {
    int n = blockIdx.x, j = threadIdx.x;
    __shared__ int   ss[64];
    __shared__ float swt[64];
    __shared__ float sa[HID];
    __shared__ float rbuf[4];
    int r0 = d_rowptr[n], r1 = d_rowptr[n + 1];
    float a0 = d_dself[n] * d_emb[n * HID + j];
    float a1 = 0.f, a2 = 0.f, a3 = 0.f;
    for (int base = r0; base < r1; base += 64) {
        int m = min(64, r1 - base);
        if (j < m) { ss[j] = d_csr_src[base + j]; swt[j] = d_csr_w[base + j]; }
        __syncthreads();
        int k = 0;
        for (; k + 4 <= m; k += 4) {
            a0 += swt[k + 0] * d_emb[ss[k + 0] * HID + j];
            a1 += swt[k + 1] * d_emb[ss[k + 1] * HID + j];
            a2 += swt[k + 2] * d_emb[ss[k + 2] * HID + j];
            a3 += swt[k + 3] * d_emb[ss[k + 3] * HID + j];
        }
        for (; k < m; k++) a0 += swt[k] * d_emb[ss[k] * HID + j];
        __syncthreads();
    }
    sa[j] = (a0 + a1) + (a2 + a3);
    __syncthreads();
    float h = bc1[j];
#pragma unroll
    for (int k = 0; k < HID; k++) h += sa[k] * Wc1[k * HID + j];
    float v = h;
#pragma unroll
    for (int o = 16; o > 0; o >>= 1) v += __shfl_xor_sync(0xffffffffu, v, o);
    if ((j & 31) == 0) rbuf[j >> 5] = v;
    __syncthreads();
    float mu = (rbuf[0] + rbuf[1]) * (1.f / 64.f);
    float d = h - mu;
    float v2 = d * d;
#pragma unroll
    for (int o = 16; o > 0; o >>= 1) v2 += __shfl_xor_sync(0xffffffffu, v2, o);
    if ((j & 31) == 0) rbuf[(j >> 5) + 2] = v2;
    __syncthreads();
    float var = (rbuf[2] + rbuf[3]) * (1.f / 64.f);
    d_r1[n * HID + j] = fmaxf(0.f, d * rsqrtf(var + 1e-5f) * g1[j] + be1[j]);
}

// ------- fused gcn layer 2: spmm64(r1) -> @Wc2 -> LN -> relu -> @Wout --------
__global__ void __launch_bounds__(64) k_gcn2(const float* __restrict__ Wc2, const float* __restrict__ bc2,
                                             const float* __restrict__ g2, const float* __restrict__ be2,
                                             const float* __restrict__ Wout, const float* __restrict__ bout,
                                             float* __restrict__ outp) {
    int n = blockIdx.x, j = threadIdx.x;
    __shared__ int   ss[64];
    __shared__ float swt[64];
    __shared__ float sa[HID];
    __shared__ float sr[HID];
    __shared__ float rbuf[4];
    int r0 = d_rowptr[n], r1 = d_rowptr[n + 1];
    float a0 = d_dself[n] * d_r1[n * HID + j];
    float a1 = 0.f, a2 = 0.f, a3 = 0.f;
    for (int base = r0; base < r1; base += 64) {
        int m = min(64, r1 - base);
        if (j < m) { ss[j] = d_csr_src[base + j]; swt[j] = d_csr_w[base + j]; }
        __syncthreads();
        int k = 0;
        for (; k + 4 <= m; k += 4) {
            a0 += swt[k + 0] * d_r1[ss[k + 0] * HID + j];
            a1 += swt[k + 1] * d_r1[ss[k + 1] * HID + j];
            a2 += swt[k + 2] * d_r1[ss[k + 2] * HID + j];
            a3 += swt[k + 3] * d_r1[ss[k + 3] * HID + j];
        }
        for (; k < m; k++) a0 += swt[k] * d_r1[ss[k] * HID + j];
        __syncthreads();
    }
    sa[j] = (a0 + a1) + (a2 + a3);
    __syncthreads();
    float h = bc2[j];
#pragma unroll
    for (int k = 0; k < HID; k++) h += sa[k] * Wc2[k * HID + j];
    float v = h;
#pragma unroll
    for (int o = 16; o > 0; o >>= 1) v += __shfl_xor_sync(0xffffffffu, v, o);
    if ((j & 31) == 0) rbuf[j >> 5] = v;
    __syncthreads();
    float mu = (rbuf[0] + rbuf[1]) * (1.f / 64.f);
    float d = h - mu;
    float v2 = d * d;
#pragma unroll
    for (int o = 16; o > 0; o >>= 1) v2 += __shfl_xor_sync(0xffffffffu, v2, o);
    if ((j & 31) == 0) rbuf[(j >> 5) + 2] = v2;
    __syncthreads();
    float var = (rbuf[2] + rbuf[3]) * (1.f / 64.f);
    float r = fmaxf(0.f, d * rsqrtf(var + 1e-5f) * g2[j] + be2[j]);
    sr[j] = r;
    __syncthreads();
    if (j < OUTD) {
        float o = bout[j];
#pragma unroll
        for (int k = 0; k < HID; k++) o += sr[k] * Wout[k * OUTD + j];
        outp[n * OUTD + j] = o;
    }
}

// ---------------- scores: relu(a_i + b_j) . w  (f32x2 packed) ----------------
// Pipe-balanced: fma pipe (add2+fma2) == alu pipe (2x FMNMX) per pair.
__global__ void __launch_bounds__(256) k_scores(const float* __restrict__ Wi2,
                                                const float* __restrict__ bi2,
                                                float* __restrict__ outp) {
    __shared__ __align__(16) float sA[64][66];
    __shared__ __align__(16) float sB[64][66];
    __shared__ __align__(16) float sW[64];
    int tx = threadIdx.x, ty = threadIdx.y;
    int tid = ty * 16 + tx;
    int i0 = blockIdx.y * 64, j0 = blockIdx.x * 64;
    for (int f = tid; f < 64 * 32; f += 256) {
        int r = f >> 5, c2 = f & 31;
        float2 va = *(const float2*)&d_av[(i0 + r) * HID + 2 * c2];
        float2 vb = *(const float2*)&d_bv[(j0 + r) * HID + 2 * c2];
        *(float2*)&sA[r][2 * c2] = va;
        *(float2*)&sB[r][2 * c2] = vb;
    }
    if (tid < 64) sW[tid] = Wi2[tid];
    __syncthreads();

    ull acc[4][4];
#pragma unroll
    for (int r = 0; r < 4; r++)
#pragma unroll
        for (int c = 0; c < 4; c++) acc[r][c] = 0ull;

#pragma unroll 4
    for (int h = 0; h < 32; h++) {
        ull w2 = *(const ull*)&sW[2 * h];
        ull A[4], B[4];
#pragma unroll
        for (int r = 0; r < 4; r++) A[r] = *(const ull*)&sA[ty * 4 + r][2 * h];
#pragma unroll
        for (int c = 0; c < 4; c++) B[c] = *(const ull*)&sB[tx * 4 + c][2 * h];
#pragma unroll
        for (int r = 0; r < 4; r++)
#pragma unroll
            for (int c = 0; c < 4; c++) {
                ull t = f2_add(A[r], B[c]);
                t = f2_relu(t);
                acc[r][c] = f2_fma(t, w2, acc[r][c]);
            }
    }

    float bb = bi2[0];
    float* sc = outp + NN * OUTD;
#pragma unroll
    for (int r = 0; r < 4; r++) {
        float4 o;
        float res[4];
#pragma unroll
        for (int c = 0; c < 4; c++) {
            float lo, hi;
            asm("mov.b64 {%0,%1},%2;" : "=f"(lo), "=f"(hi) : "l"(acc[r][c]));
            res[c] = lo + hi + bb;
        }
        o.x = res[0]; o.y = res[1]; o.z = res[2]; o.w = res[3];
        *(float4*)&sc[(i0 + ty * 4 + r) * NN + j0 + tx * 4] = o;
    }
}

// ---------------- launcher ----------------------------------------------------
extern "C" void kernel_launch(void* const* d_in, const int* in_sizes, int n_in,
                              void* d_out, int out_size) {
    (void)out_size;
    const float* x = nullptr;
    const int* ei = nullptr;
    const float* ew = nullptr;
    const float* W[28];
    int wi = 0;
    for (int i = 0; i < n_in; i++) {
        int s = in_sizes[i];
        if (s == SEQL * NN * IND)      x  = (const float*)d_in[i];
        else if (s == 2 * EE)          ei = (const int*)d_in[i];
        else if (s == EE)              ew = (const float*)d_in[i];
        else if (wi < 28)              W[wi++] = (const float*)d_in[i];
    }
    const float *Wcz = W[0],  *bcz = W[1],  *Wlz = W[2],  *blz = W[3];
    const float *Wch = W[8],  *bch = W[9],  *Wlh = W[10], *blh = W[11];
    const float *Wred = W[12], *bred = W[13];
    const float *Wc1 = W[14], *bc1 = W[15], *Wc2 = W[16], *bc2 = W[17];
    const float *g1 = W[18],  *be1 = W[19], *g2 = W[20],  *be2 = W[21];
    const float *Wout = W[22], *bout = W[23];
    const float *Wi1 = W[24], *bi1 = W[25], *Wi2 = W[26], *bi2 = W[27];
    float* outp = (float*)d_out;

    k_init<<<16, 128>>>(Wcz, bcz, Wlz, blz, Wch, bch, Wlh, blh);
    k_degcount<<<64, 1024>>>(ei, ew);
    k_scan<<<1, 1024>>>();
    k_scatter<<<64, 1024>>>(ei, ew);
    k_node<<<NN, 160>>>(x, Wred, bred, Wi1, bi1);
    k_gcn1<<<NN, 64>>>(Wc1, bc1, g1, be1);
    k_gcn2<<<NN, 64>>>(Wc2, bc2, g2, be2, Wout, bout, outp);
    k_scores<<<dim3(NN / 64, NN / 64), dim3(16, 16)>>>(Wi2, bi2, outp);
}